// round 8
// baseline (speedup 1.0000x reference)
#include <cuda_runtime.h>
#include <cuda_fp16.h>
#include <math.h>
#include <stdint.h>

// ---------------- problem constants ----------------
namespace {
constexpr int cB  = 2;
constexpr int cS  = 2048;
constexpr int cH  = 3072;
constexpr int cNH = 16;
constexpr int cHD = 256;
constexpr int cQSZ  = cNH * cHD;            // 4096
constexpr int cQKV  = 3 * cQSZ;             // 12288
constexpr int cM    = cB * cS;              // 4096 rows
}

// ---------------- scratch ----------------
__device__ float g_qkv[(size_t)cM * cQKV];          // fp32, = 64 * true qkv
__device__ __half g_hid_h[(size_t)cM * cH];         // hidden fp16
__device__ __half g_w1_h[(size_t)cQKV * cH];        // (64*Wqkv)^T fp16
__device__ __half g_at_h[(size_t)cM * cQSZ];        // attn out fp16
__device__ __half g_w2_h[(size_t)cH * cQSZ];        // (64*Wo)^T fp16
// head-major [bh][s][d] fp16 singles
__device__ __half g_qh[(size_t)cM * cQSZ];          // Q (softmax scale folded)
__device__ __half g_kh[(size_t)cM * cQSZ];
__device__ __half g_vh[(size_t)cM * cQSZ];
__device__ double g_invf[128];

// ---------------- helpers (base ISA, compute_103-safe) ----------------
__device__ __forceinline__ uint32_t smem_u32(const void* p) {
  uint32_t a;
  asm("{ .reg .u64 t; cvta.to.shared.u64 t, %1; cvt.u32.u64 %0, t; }"
      : "=r"(a) : "l"(p));
  return a;
}
#define CP_ASYNC16(dst, src) \
  asm volatile("cp.async.cg.shared.global [%0], [%1], 16;" :: "r"(dst), "l"(src))
#define CP_COMMIT() asm volatile("cp.async.commit_group;" ::: "memory")
#define CP_WAIT(n)  asm volatile("cp.async.wait_group %0;" :: "n"(n) : "memory")
#define LDSM4(r0, r1, r2, r3, addr) \
  asm volatile("ldmatrix.sync.aligned.m8n8.x4.shared.b16 {%0,%1,%2,%3}, [%4];" \
               : "=r"(r0), "=r"(r1), "=r"(r2), "=r"(r3) : "r"(addr))
#define LDSM4T(r0, r1, r2, r3, addr) \
  asm volatile("ldmatrix.sync.aligned.m8n8.x4.trans.shared.b16 {%0,%1,%2,%3}, [%4];" \
               : "=r"(r0), "=r"(r1), "=r"(r2), "=r"(r3) : "r"(addr))

__device__ __forceinline__ void mma16816(float* d, const uint32_t* a,
                                         const uint32_t* b) {
  asm volatile(
      "mma.sync.aligned.m16n8k16.row.col.f32.f16.f16.f32 "
      "{%0,%1,%2,%3}, {%4,%5,%6,%7}, {%8,%9}, {%0,%1,%2,%3};"
      : "+f"(d[0]), "+f"(d[1]), "+f"(d[2]), "+f"(d[3])
      : "r"(a[0]), "r"(a[1]), "r"(a[2]), "r"(a[3]), "r"(b[0]), "r"(b[1]));
}

__device__ __forceinline__ __half2 mk_h2(float a, float b) {
  return __halves2half2(__float2half(a), __float2half(b));
}

// ---------------- hidden fp32 -> fp16 ----------------
__global__ __launch_bounds__(256) void conv_kernel(
    const float* __restrict__ x, __half* __restrict__ h, int n4) {
  int i = blockIdx.x * 256 + threadIdx.x;
  if (i >= n4) return;
  float4 v = ((const float4*)x)[i];
  ((__half2*)h)[2 * i]     = mk_h2(v.x, v.y);
  ((__half2*)h)[2 * i + 1] = mk_h2(v.z, v.w);
}

// ---------------- transpose + scale(64) -> fp16 ----------------
__global__ __launch_bounds__(256) void tsplit_kernel(
    const float* __restrict__ W, __half* __restrict__ Th, int K, int N) {
  __shared__ float sm[32][33];
  int n0 = blockIdx.x * 32, k0 = blockIdx.y * 32;
  int tx = threadIdx.x & 31, ty = threadIdx.x >> 5;
  #pragma unroll
  for (int q = 0; q < 4; q++)
    sm[ty + 8 * q][tx] = W[(size_t)(k0 + ty + 8 * q) * N + n0 + tx];
  __syncthreads();
  #pragma unroll
  for (int q = 0; q < 4; q++) {
    float x = sm[tx][ty + 8 * q] * 64.0f;
    Th[(size_t)(n0 + ty + 8 * q) * K + k0 + tx] = __float2half(x);
  }
}

// ---------------- HMMA GEMM 128x256x32, 4-stage: C = escale * A * Bt^T ----
constexpr int BM = 128, BN = 256, BKt = 32;
constexpr int AST = 40;                      // smem row stride (halves)
constexpr int A_ELE = BM * AST;              // halves per A stage
constexpr int B_ELE = BN * AST;
constexpr int STAGEB = (A_ELE + B_ELE) * 2;  // 30720 bytes
constexpr int G_SMEM = 4 * STAGEB;           // 122880

__global__ __launch_bounds__(256, 1) void gemm_hmma(
    const __half* __restrict__ Ah, const __half* __restrict__ Bh,
    float* __restrict__ C, int M, int N, int K, float escale) {
  extern __shared__ __half smb[];
  const uint32_t sbase = smem_u32(smb);
  const int tid = threadIdx.x, lane = tid & 31, wid = tid >> 5;
  const int m0 = blockIdx.y * BM, n0 = blockIdx.x * BN;
  const int wm = (wid & 1) * 64, wn = (wid >> 1) * 64;

  float acc[4][8][4];
  #pragma unroll
  for (int i = 0; i < 4; i++)
    #pragma unroll
    for (int j = 0; j < 8; j++)
      #pragma unroll
      for (int q = 0; q < 4; q++) acc[i][j][q] = 0.0f;

  const int T = K / BKt;
  const int lr = tid >> 2, lc = tid & 3;     // loader row/col-chunk

  #define ISSUE(t)                                                          \
    do {                                                                    \
      int k0_ = (t) * BKt;                                                  \
      uint32_t db_ = sbase + ((t) & 3) * STAGEB;                            \
      _Pragma("unroll")                                                     \
      for (int i_ = 0; i_ < 2; i_++) {                                      \
        int r_ = lr + i_ * 64;                                              \
        CP_ASYNC16(db_ + (r_ * AST + lc * 8) * 2,                           \
                   Ah + (size_t)(m0 + r_) * K + k0_ + lc * 8);              \
      }                                                                     \
      _Pragma("unroll")                                                     \
      for (int i_ = 0; i_ < 4; i_++) {                                      \
        int r_ = lr + i_ * 64;                                              \
        CP_ASYNC16(db_ + (A_ELE + r_ * AST + lc * 8) * 2,                   \
                   Bh + (size_t)(n0 + r_) * K + k0_ + lc * 8);              \
      }                                                                     \
    } while (0)

  ISSUE(0); CP_COMMIT();
  ISSUE(1); CP_COMMIT();
  ISSUE(2); CP_COMMIT();

  for (int t = 0; t < T; t++) {
    CP_WAIT(2);            // stage t landed (3 groups always in flight)
    __syncthreads();       // all warps done reading stage (t-1)&3
    if (t + 3 < T) ISSUE(t + 3);
    CP_COMMIT();           // always commit (possibly empty) -> uniform count

    uint32_t base = sbase + (t & 3) * STAGEB;
    const uint32_t pA = base;
    const uint32_t pB = base + A_ELE * 2;

    #pragma unroll
    for (int ks = 0; ks < 2; ks++) {
      const int kb = ks * 16;
      uint32_t a[4][4], b[8][2];
      #pragma unroll
      for (int mt = 0; mt < 4; mt++) {
        int r = wm + mt * 16 + (lane & 15);
        int c = kb + ((lane >> 4) << 3);
        LDSM4(a[mt][0], a[mt][1], a[mt][2], a[mt][3],
              pA + (uint32_t)(r * AST + c) * 2);
      }
      #pragma unroll
      for (int p = 0; p < 4; p++) {
        int g = lane >> 3;
        int r = wn + (p * 2 + (g >> 1)) * 8 + (lane & 7);
        int c = kb + ((g & 1) << 3);
        LDSM4(b[2 * p][0], b[2 * p][1], b[2 * p + 1][0], b[2 * p + 1][1],
              pB + (uint32_t)(r * AST + c) * 2);
      }
      #pragma unroll
      for (int mt = 0; mt < 4; mt++)
        #pragma unroll
        for (int nt = 0; nt < 8; nt++) mma16816(acc[mt][nt], a[mt], b[nt]);
    }
  }
  #undef ISSUE

  #pragma unroll
  for (int mt = 0; mt < 4; mt++) {
    int row = m0 + wm + mt * 16 + (lane >> 2);
    #pragma unroll
    for (int nt = 0; nt < 8; nt++) {
      int col = n0 + wn + nt * 8 + ((lane & 3) << 1);
      *(float2*)&C[(size_t)row * N + col] =
          make_float2(acc[mt][nt][0] * escale, acc[mt][nt][1] * escale);
      *(float2*)&C[(size_t)(row + 8) * N + col] =
          make_float2(acc[mt][nt][2] * escale, acc[mt][nt][3] * escale);
    }
  }
}

// ---------------- inv_freq table ----------------
__global__ void invf_init() {
  int i = threadIdx.x;
  if (i < 128)
    g_invf[i] = exp(((double)(-2.0 * i) / 256.0) * 9.210340371976184);
}

// ---------------- RoPE: fp32 (64x) qkv -> head-major fp16 ----------------
__global__ __launch_bounds__(256) void rope_kernel(const int* __restrict__ pos) {
  int idx = blockIdx.x * 256 + threadIdx.x;
  int i   = idx & 127;
  int hh  = (idx >> 7) & 31;
  int row = idx >> 12;
  int p = pos[row];
  double ang = (double)p * g_invf[i];
  const double INV2PI = 0.15915494309189535;
  const double TWOPI  = 6.283185307179586;
  int kk = __double2int_rn(ang * INV2PI);
  float fr = (float)(ang - TWOPI * (double)kk);
  float s, c;
  __sincosf(fr, &s, &c);
  const float* base = g_qkv + (size_t)row * cQKV + hh * cHD;
  const float inv64 = 1.0f / 64.0f;
  float x1 = base[i], x2 = base[i + 128];
  float y1 = (x1 * c - x2 * s) * inv64;
  float y2 = (x2 * c + x1 * s) * inv64;
  int b = row >> 11, sidx = row & 2047;
  bool isq = hh < 16;
  int head = isq ? hh : hh - 16;
  size_t o = ((size_t)(b * cNH + head) * cS + sidx) * cHD + i;
  if (isq) {
    y1 *= 0.0625f;
    y2 *= 0.0625f;
    g_qh[o]       = __float2half(y1);
    g_qh[o + 128] = __float2half(y2);
  } else {
    g_kh[o]       = __float2half(y1);
    g_kh[o + 128] = __float2half(y2);
  }
}

// ---------------- V: fp32 (64x) -> head-major fp16 ----------------
__global__ __launch_bounds__(256) void vsplit_kernel() {
  int idx = blockIdx.x * 256 + threadIdx.x;
  int d4 = idx & 63;
  int h  = (idx >> 6) & 15;
  int row = idx >> 10;
  int b = row >> 11, sidx = row & 2047;
  const float inv64 = 1.0f / 64.0f;
  float4 v = *(const float4*)(g_qkv + (size_t)row * cQKV + 2 * cQSZ + h * cHD +
                              d4 * 4);
  size_t o = ((size_t)(b * cNH + h) * cS + sidx) * cHD + d4 * 4;
  *(__half2*)(g_vh + o)     = mk_h2(v.x * inv64, v.y * inv64);
  *(__half2*)(g_vh + o + 2) = mk_h2(v.z * inv64, v.w * inv64);
}

// ---------------- HMMA flash attention (fp16, 1-pass QK and PV) ----------
constexpr int FQST = 264;
constexpr int FPST = 72;
constexpr int F_QH = 0;
constexpr int F_KH = 1 * 64 * FQST;
constexpr int F_VH = 2 * 64 * FQST;
constexpr int F_PH = 3 * 64 * FQST;
constexpr int F_TOT = F_PH + 64 * FPST;
constexpr int FLASH_SMEM = F_TOT * 2 + 448 * 4;   // 112384 B

__global__ __launch_bounds__(256, 1) void flash_hmma(__half* __restrict__ ath) {
  extern __shared__ __half smem[];
  const uint32_t sb = smem_u32(smem);
  float* fre  = (float*)(smem + F_TOT);
  float* m_s  = fre;
  float* l_s  = fre + 64;
  float* f_s  = fre + 128;
  float* rmax = fre + 192;
  float* rsum = fre + 320;

  const int qtile = gridDim.x - 1 - blockIdx.x;
  const int bh = blockIdx.y;
  const int b = bh >> 4, h = bh & 15;
  const int tid = threadIdx.x, lane = tid & 31, wid = tid >> 5;
  const int wm = wid & 3, wg = wid >> 2;
  const int q0 = qtile * 64;

  const __half* qhb = g_qh + ((size_t)bh * cS + q0) * cHD;
  const __half* khb = g_kh + (size_t)bh * cS * cHD;
  const __half* vhb = g_vh + (size_t)bh * cS * cHD;

  #define LOADP(gptr, soff)                                              \
    do {                                                                 \
      _Pragma("unroll")                                                  \
      for (int i_ = 0; i_ < 8; i_++) {                                   \
        int id_ = tid + 256 * i_;                                        \
        int r_ = id_ >> 5, c_ = id_ & 31;                                \
        CP_ASYNC16(sb + (uint32_t)((soff) + r_ * FQST + c_ * 8) * 2,     \
                   (gptr) + r_ * 256 + c_ * 8);                          \
      }                                                                  \
    } while (0)

  LOADP(qhb, F_QH);
  LOADP(khb, F_KH);
  CP_COMMIT();
  LOADP(vhb, F_VH);
  CP_COMMIT();

  if (tid < 64) { m_s[tid] = -1e30f; l_s[tid] = 0.0f; }

  float o[16][4];
  #pragma unroll
  for (int i = 0; i < 16; i++)
    #pragma unroll
    for (int j = 0; j < 4; j++) o[i][j] = 0.0f;

  const uint32_t pQh = sb + F_QH * 2;
  const uint32_t pKh = sb + F_KH * 2;
  const uint32_t pVh = sb + F_VH * 2;
  const uint32_t pPh = sb + F_PH * 2;

  const int arow = 16 * wm + (lane & 15);
  const int acol = (lane >> 4) * 8;
  const int brow = wg * 32 + (lane & 7) + (lane >> 4) * 8;
  const int bcol = ((lane >> 3) & 1) * 8;
  const int row0 = 16 * wm + (lane >> 2);

  for (int jt = 0; jt <= qtile; jt++) {
    CP_WAIT(1);
    __syncthreads();

    // ---- S = Q K^T (1 pass) ----
    float s[4][4];
    #pragma unroll
    for (int nt = 0; nt < 4; nt++)
      #pragma unroll
      for (int c = 0; c < 4; c++) s[nt][c] = 0.0f;

    #pragma unroll 4
    for (int ks = 0; ks < 16; ks++) {
      const int k0 = ks * 16;
      uint32_t aqh[4], bkh0[4], bkh1[4];
      LDSM4(aqh[0], aqh[1], aqh[2], aqh[3],
            pQh + (uint32_t)(arow * FQST + k0 + acol) * 2);
      uint32_t boff0 = (uint32_t)(brow * FQST + k0 + bcol) * 2;
      LDSM4(bkh0[0], bkh0[1], bkh0[2], bkh0[3], pKh + boff0);
      LDSM4(bkh1[0], bkh1[1], bkh1[2], bkh1[3],
            pKh + boff0 + 16 * FQST * 2);
      uint32_t* bhp[4] = {&bkh0[0], &bkh0[2], &bkh1[0], &bkh1[2]};
      #pragma unroll
      for (int nt = 0; nt < 4; nt++) mma16816(s[nt], aqh, bhp[nt]);
    }

    // ---- causal mask ----
    if (jt == qtile) {
      #pragma unroll
      for (int nt = 0; nt < 4; nt++)
        #pragma unroll
        for (int c = 0; c < 4; c++) {
          int kvloc = wg * 32 + nt * 8 + (lane & 3) * 2 + (c & 1);
          int qloc = 16 * wm + (lane >> 2) + 8 * (c >> 1);
          if (kvloc > qloc) s[nt][c] = -1e30f;
        }
    }

    // ---- row max ----
    float lm0 = -1e30f, lm1 = -1e30f;
    #pragma unroll
    for (int nt = 0; nt < 4; nt++) {
      lm0 = fmaxf(lm0, fmaxf(s[nt][0], s[nt][1]));
      lm1 = fmaxf(lm1, fmaxf(s[nt][2], s[nt][3]));
    }
    lm0 = fmaxf(lm0, __shfl_xor_sync(0xffffffffu, lm0, 1));
    lm0 = fmaxf(lm0, __shfl_xor_sync(0xffffffffu, lm0, 2));
    lm1 = fmaxf(lm1, __shfl_xor_sync(0xffffffffu, lm1, 1));
    lm1 = fmaxf(lm1, __shfl_xor_sync(0xffffffffu, lm1, 2));
    if ((lane & 3) == 0) {
      rmax[wg * 64 + row0] = lm0;
      rmax[wg * 64 + row0 + 8] = lm1;
    }
    __syncthreads();
    if (tid < 64) {
      float mo = m_s[tid];
      float mn = fmaxf(mo, fmaxf(rmax[tid], rmax[64 + tid]));
      f_s[tid] = __expf(mo - mn);
      m_s[tid] = mn;
    }
    __syncthreads();

    // ---- exp, P store (fp16), O rescale, row sums ----
    {
      float mn0 = m_s[row0], mn1 = m_s[row0 + 8];
      float sum0 = 0.0f, sum1 = 0.0f;
      #pragma unroll
      for (int nt = 0; nt < 4; nt++) {
        float p0 = __expf(s[nt][0] - mn0);
        float p1 = __expf(s[nt][1] - mn0);
        float p2 = __expf(s[nt][2] - mn1);
        float p3 = __expf(s[nt][3] - mn1);
        sum0 += p0 + p1;
        sum1 += p2 + p3;
        int col = wg * 32 + nt * 8 + (lane & 3) * 2;
        *(__half2*)(smem + F_PH + row0 * FPST + col) = mk_h2(p0, p1);
        *(__half2*)(smem + F_PH + (row0 + 8) * FPST + col) = mk_h2(p2, p3);
      }
      sum0 += __shfl_xor_sync(0xffffffffu, sum0, 1);
      sum0 += __shfl_xor_sync(0xffffffffu, sum0, 2);
      sum1 += __shfl_xor_sync(0xffffffffu, sum1, 1);
      sum1 += __shfl_xor_sync(0xffffffffu, sum1, 2);
      if ((lane & 3) == 0) {
        rsum[wg * 64 + row0] = sum0;
        rsum[wg * 64 + row0 + 8] = sum1;
      }
      float f0 = f_s[row0], f1 = f_s[row0 + 8];
      #pragma unroll
      for (int dt = 0; dt < 16; dt++) {
        o[dt][0] *= f0; o[dt][1] *= f0;
        o[dt][2] *= f1; o[dt][3] *= f1;
      }
    }

    CP_WAIT(0);
    __syncthreads();

    if (jt < qtile) {
      LOADP(khb + (jt + 1) * 64 * 256, F_KH);
      CP_COMMIT();
    }
    if (tid < 64) l_s[tid] = l_s[tid] * f_s[tid] + rsum[tid] + rsum[64 + tid];

    // ---- O += P V (1 pass) ----
    #pragma unroll
    for (int ks = 0; ks < 4; ks++) {
      const int k0 = ks * 16;
      uint32_t aph[4];
      LDSM4(aph[0], aph[1], aph[2], aph[3],
            pPh + (uint32_t)(arow * FPST + k0 + acol) * 2);
      const int vrow = k0 + (lane & 15);
      #pragma unroll
      for (int dt2 = 0; dt2 < 8; dt2++) {
        int dbase = wg * 128 + dt2 * 16 + (lane >> 4) * 8;
        uint32_t bvh[4];
        LDSM4T(bvh[0], bvh[1], bvh[2], bvh[3],
               pVh + (uint32_t)(vrow * FQST + dbase) * 2);
        mma16816(o[dt2 * 2], aph, &bvh[0]);
        mma16816(o[dt2 * 2 + 1], aph, &bvh[2]);
      }
    }
    __syncthreads();
    if (jt < qtile) {
      LOADP(vhb + (jt + 1) * 64 * 256, F_VH);
      CP_COMMIT();
    }
  }
  #undef LOADP

  // ---- epilogue: /l, write fp16 to [b,s,h*256+d] ----
  float rl0 = 1.0f / l_s[row0];
  float rl1 = 1.0f / l_s[row0 + 8];
  size_t g0 = ((size_t)(b * cS + q0 + row0)) * cQSZ + h * cHD;
  size_t g1 = g0 + 8 * cQSZ;
  #pragma unroll
  for (int dt = 0; dt < 16; dt++) {
    int col = wg * 128 + dt * 8 + (lane & 3) * 2;
    *(__half2*)(ath + g0 + col) = mk_h2(o[dt][0] * rl0, o[dt][1] * rl0);
    *(__half2*)(ath + g1 + col) = mk_h2(o[dt][2] * rl1, o[dt][3] * rl1);
  }
}

// ---------------- launch ----------------
extern "C" void kernel_launch(void* const* d_in, const int* in_sizes, int n_in,
                              void* d_out, int out_size) {
  (void)in_sizes; (void)n_in; (void)out_size;
  const float* hidden = (const float*)d_in[0];
  const int*   pos    = (const int*)d_in[1];
  const float* Wqkv   = (const float*)d_in[2];
  const float* Wo     = (const float*)d_in[3];
  float* out = (float*)d_out;

  float* qkv_p;
  __half *hidh, *w1h, *ath, *w2h;
  cudaGetSymbolAddress((void**)&qkv_p, g_qkv);
  cudaGetSymbolAddress((void**)&hidh, g_hid_h);
  cudaGetSymbolAddress((void**)&w1h, g_w1_h);
  cudaGetSymbolAddress((void**)&ath, g_at_h);
  cudaGetSymbolAddress((void**)&w2h, g_w2_h);

  cudaFuncSetAttribute(gemm_hmma,
                       cudaFuncAttributeMaxDynamicSharedMemorySize, G_SMEM);
  cudaFuncSetAttribute(flash_hmma,
                       cudaFuncAttributeMaxDynamicSharedMemorySize, FLASH_SMEM);

  invf_init<<<1, 128>>>();
  {
    int n4 = cM * cH / 4;
    conv_kernel<<<(n4 + 255) / 256, 256>>>(hidden, hidh, n4);
    tsplit_kernel<<<dim3(cQKV / 32, cH / 32), 256>>>(Wqkv, w1h, cH, cQKV);
    tsplit_kernel<<<dim3(cH / 32, cQSZ / 32), 256>>>(Wo, w2h, cQSZ, cH);
  }
  // QKV projection: 1 pass, 128x256 tile. C = 64 * qkv.
  gemm_hmma<<<dim3(cQKV / BN, cM / BM), 256, G_SMEM>>>(
      hidh, w1h, qkv_p, cM, cQKV, cH, 1.0f);
  rope_kernel<<<(cM * 32 * 128) / 256, 256>>>(pos);
  vsplit_kernel<<<(cM * cQSZ / 4) / 256, 256>>>();
  flash_hmma<<<dim3(cS / 64, cB * cNH), 256, FLASH_SMEM>>>(ath);
  // output projection: 1 pass, 128x256 tile. C = 64 * out -> /64.
  gemm_hmma<<<dim3(cH / BN, cM / BM), 256, G_SMEM>>>(
      ath, w2h, out, cM, cH, cQSZ, 1.0f / 64.0f);
}

// round 9
// speedup vs baseline: 1.1130x; 1.1130x over previous
#include <cuda_runtime.h>
#include <cuda_fp16.h>
#include <math.h>
#include <stdint.h>

// ---------------- problem constants ----------------
namespace {
constexpr int cB  = 2;
constexpr int cS  = 2048;
constexpr int cH  = 3072;
constexpr int cNH = 16;
constexpr int cHD = 256;
constexpr int cQSZ  = cNH * cHD;            // 4096
constexpr int cQKV  = 3 * cQSZ;             // 12288
constexpr int cM    = cB * cS;              // 4096 rows
}

// ---------------- scratch ----------------
__device__ float g_qkv[(size_t)cM * cQKV];          // fp32, = 64 * true qkv
__device__ __half g_hid_h[(size_t)cM * cH];         // hidden fp16
__device__ __half g_w1_h[(size_t)cQKV * cH];        // (64*Wqkv)^T fp16
__device__ __half g_at_h[(size_t)cM * cQSZ];        // attn out fp16
__device__ __half g_w2_h[(size_t)cH * cQSZ];        // (64*Wo)^T fp16
// head-major [bh][s][d] fp16 singles
__device__ __half g_qh[(size_t)cM * cQSZ];          // Q (softmax scale folded)
__device__ __half g_kh[(size_t)cM * cQSZ];
__device__ __half g_vh[(size_t)cM * cQSZ];
__device__ double g_invf[128];

// ---------------- helpers (base ISA, compute_103-safe) ----------------
__device__ __forceinline__ uint32_t smem_u32(const void* p) {
  uint32_t a;
  asm("{ .reg .u64 t; cvta.to.shared.u64 t, %1; cvt.u32.u64 %0, t; }"
      : "=r"(a) : "l"(p));
  return a;
}
#define CP_ASYNC16(dst, src) \
  asm volatile("cp.async.cg.shared.global [%0], [%1], 16;" :: "r"(dst), "l"(src))
#define CP_COMMIT() asm volatile("cp.async.commit_group;" ::: "memory")
#define CP_WAIT(n)  asm volatile("cp.async.wait_group %0;" :: "n"(n) : "memory")
#define LDSM4(r0, r1, r2, r3, addr) \
  asm volatile("ldmatrix.sync.aligned.m8n8.x4.shared.b16 {%0,%1,%2,%3}, [%4];" \
               : "=r"(r0), "=r"(r1), "=r"(r2), "=r"(r3) : "r"(addr))
#define LDSM4T(r0, r1, r2, r3, addr) \
  asm volatile("ldmatrix.sync.aligned.m8n8.x4.trans.shared.b16 {%0,%1,%2,%3}, [%4];" \
               : "=r"(r0), "=r"(r1), "=r"(r2), "=r"(r3) : "r"(addr))

__device__ __forceinline__ void mma16816(float* d, const uint32_t* a,
                                         const uint32_t* b) {
  asm volatile(
      "mma.sync.aligned.m16n8k16.row.col.f32.f16.f16.f32 "
      "{%0,%1,%2,%3}, {%4,%5,%6,%7}, {%8,%9}, {%0,%1,%2,%3};"
      : "+f"(d[0]), "+f"(d[1]), "+f"(d[2]), "+f"(d[3])
      : "r"(a[0]), "r"(a[1]), "r"(a[2]), "r"(a[3]), "r"(b[0]), "r"(b[1]));
}

__device__ __forceinline__ __half2 mk_h2(float a, float b) {
  return __halves2half2(__float2half(a), __float2half(b));
}

// ---------------- hidden fp32 -> fp16 ----------------
__global__ __launch_bounds__(256) void conv_kernel(
    const float* __restrict__ x, __half* __restrict__ h, int n4) {
  int i = blockIdx.x * 256 + threadIdx.x;
  if (i >= n4) return;
  float4 v = ((const float4*)x)[i];
  ((__half2*)h)[2 * i]     = mk_h2(v.x, v.y);
  ((__half2*)h)[2 * i + 1] = mk_h2(v.z, v.w);
}

// ---------------- transpose + scale(64) -> fp16 ----------------
__global__ __launch_bounds__(256) void tsplit_kernel(
    const float* __restrict__ W, __half* __restrict__ Th, int K, int N) {
  __shared__ float sm[32][33];
  int n0 = blockIdx.x * 32, k0 = blockIdx.y * 32;
  int tx = threadIdx.x & 31, ty = threadIdx.x >> 5;
  #pragma unroll
  for (int q = 0; q < 4; q++)
    sm[ty + 8 * q][tx] = W[(size_t)(k0 + ty + 8 * q) * N + n0 + tx];
  __syncthreads();
  #pragma unroll
  for (int q = 0; q < 4; q++) {
    float x = sm[tx][ty + 8 * q] * 64.0f;
    Th[(size_t)(n0 + ty + 8 * q) * K + k0 + tx] = __float2half(x);
  }
}

// ---------------- HMMA GEMM 128x128x32, 3-stage, 2 CTA/SM ----------------
constexpr int BM = 128, BN = 128, BKt = 32;
constexpr int AST = 40;                      // smem row stride (halves)
constexpr int PARTE = BM * AST;              // halves per part (A or B)
constexpr int STAGEB = 2 * PARTE * 2;        // 20480 bytes per stage
constexpr int G_SMEM = 3 * STAGEB;           // 61440

__global__ __launch_bounds__(256, 2) void gemm_hmma(
    const __half* __restrict__ Ah, const __half* __restrict__ Bh,
    float* __restrict__ C, int M, int N, int K, float escale) {
  extern __shared__ __half smb[];
  const uint32_t sbase = smem_u32(smb);
  const int tid = threadIdx.x, lane = tid & 31, wid = tid >> 5;
  const int m0 = blockIdx.y * BM, n0 = blockIdx.x * BN;
  const int wm = (wid & 1) * 64, wn = (wid >> 1) * 32;

  float acc[4][4][4];
  #pragma unroll
  for (int i = 0; i < 4; i++)
    #pragma unroll
    for (int j = 0; j < 4; j++)
      #pragma unroll
      for (int q = 0; q < 4; q++) acc[i][j][q] = 0.0f;

  const int T = K / BKt;
  const int lr = tid >> 2, lc = tid & 3;     // loader row / 16B-chunk

  #define ISSUE(t)                                                          \
    do {                                                                    \
      int k0_ = (t) * BKt;                                                  \
      uint32_t db_ = sbase + ((t) % 3) * STAGEB;                            \
      _Pragma("unroll")                                                     \
      for (int i_ = 0; i_ < 2; i_++) {                                      \
        int r_ = lr + i_ * 64;                                              \
        uint32_t o_ = (r_ * AST + lc * 8) * 2;                              \
        CP_ASYNC16(db_ + o_, Ah + (size_t)(m0 + r_) * K + k0_ + lc * 8);    \
        CP_ASYNC16(db_ + PARTE * 2 + o_,                                    \
                   Bh + (size_t)(n0 + r_) * K + k0_ + lc * 8);              \
      }                                                                     \
    } while (0)

  ISSUE(0); CP_COMMIT();
  ISSUE(1); CP_COMMIT();

  for (int t = 0; t < T; t++) {
    CP_WAIT(1);            // stage t landed
    __syncthreads();       // everyone past reads of stage (t-1)%3
    if (t + 2 < T) { ISSUE(t + 2); CP_COMMIT(); }

    uint32_t base = sbase + (t % 3) * STAGEB;
    const uint32_t pA = base;
    const uint32_t pB = base + PARTE * 2;

    #pragma unroll
    for (int ks = 0; ks < 2; ks++) {
      const int kb = ks * 16;
      uint32_t a[4][4], b[4][2];
      #pragma unroll
      for (int mt = 0; mt < 4; mt++) {
        int r = wm + mt * 16 + (lane & 15);
        int c = kb + ((lane >> 4) << 3);
        LDSM4(a[mt][0], a[mt][1], a[mt][2], a[mt][3],
              pA + (uint32_t)(r * AST + c) * 2);
      }
      #pragma unroll
      for (int p = 0; p < 2; p++) {
        int g = lane >> 3;
        int r = wn + (p * 2 + (g >> 1)) * 8 + (lane & 7);
        int c = kb + ((g & 1) << 3);
        LDSM4(b[2 * p][0], b[2 * p][1], b[2 * p + 1][0], b[2 * p + 1][1],
              pB + (uint32_t)(r * AST + c) * 2);
      }
      #pragma unroll
      for (int mt = 0; mt < 4; mt++)
        #pragma unroll
        for (int nt = 0; nt < 4; nt++) mma16816(acc[mt][nt], a[mt], b[nt]);
    }
  }
  #undef ISSUE

  #pragma unroll
  for (int mt = 0; mt < 4; mt++) {
    int row = m0 + wm + mt * 16 + (lane >> 2);
    #pragma unroll
    for (int nt = 0; nt < 4; nt++) {
      int col = n0 + wn + nt * 8 + ((lane & 3) << 1);
      *(float2*)&C[(size_t)row * N + col] =
          make_float2(acc[mt][nt][0] * escale, acc[mt][nt][1] * escale);
      *(float2*)&C[(size_t)(row + 8) * N + col] =
          make_float2(acc[mt][nt][2] * escale, acc[mt][nt][3] * escale);
    }
  }
}

// ---------------- inv_freq table ----------------
__global__ void invf_init() {
  int i = threadIdx.x;
  if (i < 128)
    g_invf[i] = exp(((double)(-2.0 * i) / 256.0) * 9.210340371976184);
}

// ---------------- RoPE: fp32 (64x) qkv -> head-major fp16 ----------------
__global__ __launch_bounds__(256) void rope_kernel(const int* __restrict__ pos) {
  int idx = blockIdx.x * 256 + threadIdx.x;
  int i   = idx & 127;
  int hh  = (idx >> 7) & 31;
  int row = idx >> 12;
  int p = pos[row];
  double ang = (double)p * g_invf[i];
  const double INV2PI = 0.15915494309189535;
  const double TWOPI  = 6.283185307179586;
  int kk = __double2int_rn(ang * INV2PI);
  float fr = (float)(ang - TWOPI * (double)kk);
  float s, c;
  __sincosf(fr, &s, &c);
  const float* base = g_qkv + (size_t)row * cQKV + hh * cHD;
  const float inv64 = 1.0f / 64.0f;
  float x1 = base[i], x2 = base[i + 128];
  float y1 = (x1 * c - x2 * s) * inv64;
  float y2 = (x2 * c + x1 * s) * inv64;
  int b = row >> 11, sidx = row & 2047;
  bool isq = hh < 16;
  int head = isq ? hh : hh - 16;
  size_t o = ((size_t)(b * cNH + head) * cS + sidx) * cHD + i;
  if (isq) {
    y1 *= 0.0625f;
    y2 *= 0.0625f;
    g_qh[o]       = __float2half(y1);
    g_qh[o + 128] = __float2half(y2);
  } else {
    g_kh[o]       = __float2half(y1);
    g_kh[o + 128] = __float2half(y2);
  }
}

// ---------------- V: fp32 (64x) -> head-major fp16 ----------------
__global__ __launch_bounds__(256) void vsplit_kernel() {
  int idx = blockIdx.x * 256 + threadIdx.x;
  int d4 = idx & 63;
  int h  = (idx >> 6) & 15;
  int row = idx >> 10;
  int b = row >> 11, sidx = row & 2047;
  const float inv64 = 1.0f / 64.0f;
  float4 v = *(const float4*)(g_qkv + (size_t)row * cQKV + 2 * cQSZ + h * cHD +
                              d4 * 4);
  size_t o = ((size_t)(b * cNH + h) * cS + sidx) * cHD + d4 * 4;
  *(__half2*)(g_vh + o)     = mk_h2(v.x * inv64, v.y * inv64);
  *(__half2*)(g_vh + o + 2) = mk_h2(v.z * inv64, v.w * inv64);
}

// ---------------- HMMA flash attention (fp16, 1-pass QK and PV) ----------
constexpr int FQST = 264;
constexpr int FPST = 72;
constexpr int F_QH = 0;
constexpr int F_KH = 1 * 64 * FQST;
constexpr int F_VH = 2 * 64 * FQST;
constexpr int F_PH = 3 * 64 * FQST;
constexpr int F_TOT = F_PH + 64 * FPST;
constexpr int FLASH_SMEM = F_TOT * 2 + 448 * 4;   // 112384 B

__global__ __launch_bounds__(256, 1) void flash_hmma(__half* __restrict__ ath) {
  extern __shared__ __half smem[];
  const uint32_t sb = smem_u32(smem);
  float* fre  = (float*)(smem + F_TOT);
  float* m_s  = fre;
  float* l_s  = fre + 64;
  float* f_s  = fre + 128;
  float* rmax = fre + 192;
  float* rsum = fre + 320;

  const int qtile = gridDim.x - 1 - blockIdx.x;
  const int bh = blockIdx.y;
  const int b = bh >> 4, h = bh & 15;
  const int tid = threadIdx.x, lane = tid & 31, wid = tid >> 5;
  const int wm = wid & 3, wg = wid >> 2;
  const int q0 = qtile * 64;

  const __half* qhb = g_qh + ((size_t)bh * cS + q0) * cHD;
  const __half* khb = g_kh + (size_t)bh * cS * cHD;
  const __half* vhb = g_vh + (size_t)bh * cS * cHD;

  #define LOADP(gptr, soff)                                              \
    do {                                                                 \
      _Pragma("unroll")                                                  \
      for (int i_ = 0; i_ < 8; i_++) {                                   \
        int id_ = tid + 256 * i_;                                        \
        int r_ = id_ >> 5, c_ = id_ & 31;                                \
        CP_ASYNC16(sb + (uint32_t)((soff) + r_ * FQST + c_ * 8) * 2,     \
                   (gptr) + r_ * 256 + c_ * 8);                          \
      }                                                                  \
    } while (0)

  LOADP(qhb, F_QH);
  LOADP(khb, F_KH);
  CP_COMMIT();
  LOADP(vhb, F_VH);
  CP_COMMIT();

  if (tid < 64) { m_s[tid] = -1e30f; l_s[tid] = 0.0f; }

  float o[16][4];
  #pragma unroll
  for (int i = 0; i < 16; i++)
    #pragma unroll
    for (int j = 0; j < 4; j++) o[i][j] = 0.0f;

  const uint32_t pQh = sb + F_QH * 2;
  const uint32_t pKh = sb + F_KH * 2;
  const uint32_t pVh = sb + F_VH * 2;
  const uint32_t pPh = sb + F_PH * 2;

  const int arow = 16 * wm + (lane & 15);
  const int acol = (lane >> 4) * 8;
  const int brow = wg * 32 + (lane & 7) + (lane >> 4) * 8;
  const int bcol = ((lane >> 3) & 1) * 8;
  const int row0 = 16 * wm + (lane >> 2);

  for (int jt = 0; jt <= qtile; jt++) {
    CP_WAIT(1);
    __syncthreads();

    // ---- S = Q K^T (1 pass) ----
    float s[4][4];
    #pragma unroll
    for (int nt = 0; nt < 4; nt++)
      #pragma unroll
      for (int c = 0; c < 4; c++) s[nt][c] = 0.0f;

    #pragma unroll 4
    for (int ks = 0; ks < 16; ks++) {
      const int k0 = ks * 16;
      uint32_t aqh[4], bkh0[4], bkh1[4];
      LDSM4(aqh[0], aqh[1], aqh[2], aqh[3],
            pQh + (uint32_t)(arow * FQST + k0 + acol) * 2);
      uint32_t boff0 = (uint32_t)(brow * FQST + k0 + bcol) * 2;
      LDSM4(bkh0[0], bkh0[1], bkh0[2], bkh0[3], pKh + boff0);
      LDSM4(bkh1[0], bkh1[1], bkh1[2], bkh1[3],
            pKh + boff0 + 16 * FQST * 2);
      uint32_t* bhp[4] = {&bkh0[0], &bkh0[2], &bkh1[0], &bkh1[2]};
      #pragma unroll
      for (int nt = 0; nt < 4; nt++) mma16816(s[nt], aqh, bhp[nt]);
    }

    // ---- causal mask ----
    if (jt == qtile) {
      #pragma unroll
      for (int nt = 0; nt < 4; nt++)
        #pragma unroll
        for (int c = 0; c < 4; c++) {
          int kvloc = wg * 32 + nt * 8 + (lane & 3) * 2 + (c & 1);
          int qloc = 16 * wm + (lane >> 2) + 8 * (c >> 1);
          if (kvloc > qloc) s[nt][c] = -1e30f;
        }
    }

    // ---- row max ----
    float lm0 = -1e30f, lm1 = -1e30f;
    #pragma unroll
    for (int nt = 0; nt < 4; nt++) {
      lm0 = fmaxf(lm0, fmaxf(s[nt][0], s[nt][1]));
      lm1 = fmaxf(lm1, fmaxf(s[nt][2], s[nt][3]));
    }
    lm0 = fmaxf(lm0, __shfl_xor_sync(0xffffffffu, lm0, 1));
    lm0 = fmaxf(lm0, __shfl_xor_sync(0xffffffffu, lm0, 2));
    lm1 = fmaxf(lm1, __shfl_xor_sync(0xffffffffu, lm1, 1));
    lm1 = fmaxf(lm1, __shfl_xor_sync(0xffffffffu, lm1, 2));
    if ((lane & 3) == 0) {
      rmax[wg * 64 + row0] = lm0;
      rmax[wg * 64 + row0 + 8] = lm1;
    }
    __syncthreads();
    if (tid < 64) {
      float mo = m_s[tid];
      float mn = fmaxf(mo, fmaxf(rmax[tid], rmax[64 + tid]));
      f_s[tid] = __expf(mo - mn);
      m_s[tid] = mn;
    }
    __syncthreads();

    // ---- exp, P store (fp16), O rescale, row sums ----
    {
      float mn0 = m_s[row0], mn1 = m_s[row0 + 8];
      float sum0 = 0.0f, sum1 = 0.0f;
      #pragma unroll
      for (int nt = 0; nt < 4; nt++) {
        float p0 = __expf(s[nt][0] - mn0);
        float p1 = __expf(s[nt][1] - mn0);
        float p2 = __expf(s[nt][2] - mn1);
        float p3 = __expf(s[nt][3] - mn1);
        sum0 += p0 + p1;
        sum1 += p2 + p3;
        int col = wg * 32 + nt * 8 + (lane & 3) * 2;
        *(__half2*)(smem + F_PH + row0 * FPST + col) = mk_h2(p0, p1);
        *(__half2*)(smem + F_PH + (row0 + 8) * FPST + col) = mk_h2(p2, p3);
      }
      sum0 += __shfl_xor_sync(0xffffffffu, sum0, 1);
      sum0 += __shfl_xor_sync(0xffffffffu, sum0, 2);
      sum1 += __shfl_xor_sync(0xffffffffu, sum1, 1);
      sum1 += __shfl_xor_sync(0xffffffffu, sum1, 2);
      if ((lane & 3) == 0) {
        rsum[wg * 64 + row0] = sum0;
        rsum[wg * 64 + row0 + 8] = sum1;
      }
      float f0 = f_s[row0], f1 = f_s[row0 + 8];
      #pragma unroll
      for (int dt = 0; dt < 16; dt++) {
        o[dt][0] *= f0; o[dt][1] *= f0;
        o[dt][2] *= f1; o[dt][3] *= f1;
      }
    }

    CP_WAIT(0);
    __syncthreads();

    if (jt < qtile) {
      LOADP(khb + (jt + 1) * 64 * 256, F_KH);
      CP_COMMIT();
    }
    if (tid < 64) l_s[tid] = l_s[tid] * f_s[tid] + rsum[tid] + rsum[64 + tid];

    // ---- O += P V (1 pass) ----
    #pragma unroll
    for (int ks = 0; ks < 4; ks++) {
      const int k0 = ks * 16;
      uint32_t aph[4];
      LDSM4(aph[0], aph[1], aph[2], aph[3],
            pPh + (uint32_t)(arow * FPST + k0 + acol) * 2);
      const int vrow = k0 + (lane & 15);
      #pragma unroll
      for (int dt2 = 0; dt2 < 8; dt2++) {
        int dbase = wg * 128 + dt2 * 16 + (lane >> 4) * 8;
        uint32_t bvh[4];
        LDSM4T(bvh[0], bvh[1], bvh[2], bvh[3],
               pVh + (uint32_t)(vrow * FQST + dbase) * 2);
        mma16816(o[dt2 * 2], aph, &bvh[0]);
        mma16816(o[dt2 * 2 + 1], aph, &bvh[2]);
      }
    }
    __syncthreads();
    if (jt < qtile) {
      LOADP(vhb + (jt + 1) * 64 * 256, F_VH);
      CP_COMMIT();
    }
  }
  #undef LOADP

  // ---- epilogue: /l, write fp16 to [b,s,h*256+d] ----
  float rl0 = 1.0f / l_s[row0];
  float rl1 = 1.0f / l_s[row0 + 8];
  size_t g0 = ((size_t)(b * cS + q0 + row0)) * cQSZ + h * cHD;
  size_t g1 = g0 + 8 * cQSZ;
  #pragma unroll
  for (int dt = 0; dt < 16; dt++) {
    int col = wg * 128 + dt * 8 + (lane & 3) * 2;
    *(__half2*)(ath + g0 + col) = mk_h2(o[dt][0] * rl0, o[dt][1] * rl0);
    *(__half2*)(ath + g1 + col) = mk_h2(o[dt][2] * rl1, o[dt][3] * rl1);
  }
}

// ---------------- launch ----------------
extern "C" void kernel_launch(void* const* d_in, const int* in_sizes, int n_in,
                              void* d_out, int out_size) {
  (void)in_sizes; (void)n_in; (void)out_size;
  const float* hidden = (const float*)d_in[0];
  const int*   pos    = (const int*)d_in[1];
  const float* Wqkv   = (const float*)d_in[2];
  const float* Wo     = (const float*)d_in[3];
  float* out = (float*)d_out;

  float* qkv_p;
  __half *hidh, *w1h, *ath, *w2h;
  cudaGetSymbolAddress((void**)&qkv_p, g_qkv);
  cudaGetSymbolAddress((void**)&hidh, g_hid_h);
  cudaGetSymbolAddress((void**)&w1h, g_w1_h);
  cudaGetSymbolAddress((void**)&ath, g_at_h);
  cudaGetSymbolAddress((void**)&w2h, g_w2_h);

  cudaFuncSetAttribute(gemm_hmma,
                       cudaFuncAttributeMaxDynamicSharedMemorySize, G_SMEM);
  cudaFuncSetAttribute(flash_hmma,
                       cudaFuncAttributeMaxDynamicSharedMemorySize, FLASH_SMEM);

  invf_init<<<1, 128>>>();
  {
    int n4 = cM * cH / 4;
    conv_kernel<<<(n4 + 255) / 256, 256>>>(hidden, hidh, n4);
    tsplit_kernel<<<dim3(cQKV / 32, cH / 32), 256>>>(Wqkv, w1h, cH, cQKV);
    tsplit_kernel<<<dim3(cH / 32, cQSZ / 32), 256>>>(Wo, w2h, cQSZ, cH);
  }
  // QKV projection: 1 pass, 128x128 tile, 3-stage. C = 64 * qkv.
  gemm_hmma<<<dim3(cQKV / BN, cM / BM), 256, G_SMEM>>>(
      hidh, w1h, qkv_p, cM, cQKV, cH, 1.0f);
  rope_kernel<<<(cM * 32 * 128) / 256, 256>>>(pos);
  vsplit_kernel<<<(cM * cQSZ / 4) / 256, 256>>>();
  flash_hmma<<<dim3(cS / 64, cB * cNH), 256, FLASH_SMEM>>>(ath);
  // output projection: 1 pass, 128x128 tile, 3-stage. C = 64 * out -> /64.
  gemm_hmma<<<dim3(cH / BN, cM / BM), 256, G_SMEM>>>(
      ath, w2h, out, cM, cH, cQSZ, 1.0f / 64.0f);
}

// round 10
// speedup vs baseline: 1.2456x; 1.1191x over previous
#include <cuda_runtime.h>
#include <cuda_fp16.h>
#include <math.h>
#include <stdint.h>

// ---------------- problem constants ----------------
namespace {
constexpr int cB  = 2;
constexpr int cS  = 2048;
constexpr int cH  = 3072;
constexpr int cNH = 16;
constexpr int cHD = 256;
constexpr int cQSZ  = cNH * cHD;            // 4096
constexpr int cQKV  = 3 * cQSZ;             // 12288
constexpr int cM    = cB * cS;              // 4096 rows
}

// ---------------- scratch ----------------
__device__ float g_qkv[(size_t)cM * cQKV];          // fp32, = 64 * true qkv
__device__ __half g_hid_h[(size_t)cM * cH];         // hidden fp16
__device__ __half g_w1_h[(size_t)cQKV * cH];        // (64*Wqkv)^T fp16
__device__ __half g_at_h[(size_t)cM * cQSZ];        // attn out fp16
__device__ __half g_w2_h[(size_t)cH * cQSZ];        // (64*Wo)^T fp16
// head-major [bh][s][d] fp16 singles
__device__ __half g_qh[(size_t)cM * cQSZ];          // Q (softmax scale folded)
__device__ __half g_kh[(size_t)cM * cQSZ];
__device__ __half g_vh[(size_t)cM * cQSZ];
__device__ double g_invf[128];

// ---------------- helpers (base ISA, compute_103-safe) ----------------
__device__ __forceinline__ uint32_t smem_u32(const void* p) {
  uint32_t a;
  asm("{ .reg .u64 t; cvta.to.shared.u64 t, %1; cvt.u32.u64 %0, t; }"
      : "=r"(a) : "l"(p));
  return a;
}
#define CP_ASYNC16(dst, src) \
  asm volatile("cp.async.cg.shared.global [%0], [%1], 16;" :: "r"(dst), "l"(src))
#define CP_COMMIT() asm volatile("cp.async.commit_group;" ::: "memory")
#define CP_WAIT(n)  asm volatile("cp.async.wait_group %0;" :: "n"(n) : "memory")
#define LDSM4(r0, r1, r2, r3, addr) \
  asm volatile("ldmatrix.sync.aligned.m8n8.x4.shared.b16 {%0,%1,%2,%3}, [%4];" \
               : "=r"(r0), "=r"(r1), "=r"(r2), "=r"(r3) : "r"(addr))
#define LDSM4T(r0, r1, r2, r3, addr) \
  asm volatile("ldmatrix.sync.aligned.m8n8.x4.trans.shared.b16 {%0,%1,%2,%3}, [%4];" \
               : "=r"(r0), "=r"(r1), "=r"(r2), "=r"(r3) : "r"(addr))

__device__ __forceinline__ void mma16816(float* d, const uint32_t* a,
                                         const uint32_t* b) {
  asm volatile(
      "mma.sync.aligned.m16n8k16.row.col.f32.f16.f16.f32 "
      "{%0,%1,%2,%3}, {%4,%5,%6,%7}, {%8,%9}, {%0,%1,%2,%3};"
      : "+f"(d[0]), "+f"(d[1]), "+f"(d[2]), "+f"(d[3])
      : "r"(a[0]), "r"(a[1]), "r"(a[2]), "r"(a[3]), "r"(b[0]), "r"(b[1]));
}

__device__ __forceinline__ __half2 mk_h2(float a, float b) {
  return __halves2half2(__float2half(a), __float2half(b));
}

// ---------------- hidden fp32 -> fp16 ----------------
__global__ __launch_bounds__(256) void conv_kernel(
    const float* __restrict__ x, __half* __restrict__ h, int n4) {
  int i = blockIdx.x * 256 + threadIdx.x;
  if (i >= n4) return;
  float4 v = ((const float4*)x)[i];
  ((__half2*)h)[2 * i]     = mk_h2(v.x, v.y);
  ((__half2*)h)[2 * i + 1] = mk_h2(v.z, v.w);
}

// ---------------- transpose + scale(64) -> fp16 ----------------
__global__ __launch_bounds__(256) void tsplit_kernel(
    const float* __restrict__ W, __half* __restrict__ Th, int K, int N) {
  __shared__ float sm[32][33];
  int n0 = blockIdx.x * 32, k0 = blockIdx.y * 32;
  int tx = threadIdx.x & 31, ty = threadIdx.x >> 5;
  #pragma unroll
  for (int q = 0; q < 4; q++)
    sm[ty + 8 * q][tx] = W[(size_t)(k0 + ty + 8 * q) * N + n0 + tx];
  __syncthreads();
  #pragma unroll
  for (int q = 0; q < 4; q++) {
    float x = sm[tx][ty + 8 * q] * 64.0f;
    Th[(size_t)(n0 + ty + 8 * q) * K + k0 + tx] = __float2half(x);
  }
}

// ---------------- HMMA GEMM 128x128x32, 3-stage, 2 CTA/SM ----------------
constexpr int BM = 128, BN = 128, BKt = 32;
constexpr int AST = 40;                      // smem row stride (halves)
constexpr int PARTE = BM * AST;              // halves per part (A or B)
constexpr int STAGEB = 2 * PARTE * 2;        // 20480 bytes per stage
constexpr int G_SMEM = 3 * STAGEB;           // 61440

__global__ __launch_bounds__(256, 2) void gemm_hmma(
    const __half* __restrict__ Ah, const __half* __restrict__ Bh,
    float* __restrict__ C, int M, int N, int K, float escale) {
  extern __shared__ __half smb[];
  const uint32_t sbase = smem_u32(smb);
  const int tid = threadIdx.x, lane = tid & 31, wid = tid >> 5;
  const int m0 = blockIdx.y * BM, n0 = blockIdx.x * BN;
  const int wm = (wid & 1) * 64, wn = (wid >> 1) * 32;

  float acc[4][4][4];
  #pragma unroll
  for (int i = 0; i < 4; i++)
    #pragma unroll
    for (int j = 0; j < 4; j++)
      #pragma unroll
      for (int q = 0; q < 4; q++) acc[i][j][q] = 0.0f;

  const int T = K / BKt;
  const int lr = tid >> 2, lc = tid & 3;     // loader row / 16B-chunk

  #define ISSUE(t)                                                          \
    do {                                                                    \
      int k0_ = (t) * BKt;                                                  \
      uint32_t db_ = sbase + ((t) % 3) * STAGEB;                            \
      _Pragma("unroll")                                                     \
      for (int i_ = 0; i_ < 2; i_++) {                                      \
        int r_ = lr + i_ * 64;                                              \
        uint32_t o_ = (r_ * AST + lc * 8) * 2;                              \
        CP_ASYNC16(db_ + o_, Ah + (size_t)(m0 + r_) * K + k0_ + lc * 8);    \
        CP_ASYNC16(db_ + PARTE * 2 + o_,                                    \
                   Bh + (size_t)(n0 + r_) * K + k0_ + lc * 8);              \
      }                                                                     \
    } while (0)

  ISSUE(0); CP_COMMIT();
  ISSUE(1); CP_COMMIT();

  for (int t = 0; t < T; t++) {
    CP_WAIT(1);            // stage t landed
    __syncthreads();       // everyone past reads of stage (t-1)%3
    if (t + 2 < T) { ISSUE(t + 2); CP_COMMIT(); }

    uint32_t base = sbase + (t % 3) * STAGEB;
    const uint32_t pA = base;
    const uint32_t pB = base + PARTE * 2;

    #pragma unroll
    for (int ks = 0; ks < 2; ks++) {
      const int kb = ks * 16;
      uint32_t a[4][4], b[4][2];
      #pragma unroll
      for (int mt = 0; mt < 4; mt++) {
        int r = wm + mt * 16 + (lane & 15);
        int c = kb + ((lane >> 4) << 3);
        LDSM4(a[mt][0], a[mt][1], a[mt][2], a[mt][3],
              pA + (uint32_t)(r * AST + c) * 2);
      }
      #pragma unroll
      for (int p = 0; p < 2; p++) {
        int g = lane >> 3;
        int r = wn + (p * 2 + (g >> 1)) * 8 + (lane & 7);
        int c = kb + ((g & 1) << 3);
        LDSM4(b[2 * p][0], b[2 * p][1], b[2 * p + 1][0], b[2 * p + 1][1],
              pB + (uint32_t)(r * AST + c) * 2);
      }
      #pragma unroll
      for (int mt = 0; mt < 4; mt++)
        #pragma unroll
        for (int nt = 0; nt < 4; nt++) mma16816(acc[mt][nt], a[mt], b[nt]);
    }
  }
  #undef ISSUE

  #pragma unroll
  for (int mt = 0; mt < 4; mt++) {
    int row = m0 + wm + mt * 16 + (lane >> 2);
    #pragma unroll
    for (int nt = 0; nt < 4; nt++) {
      int col = n0 + wn + nt * 8 + ((lane & 3) << 1);
      *(float2*)&C[(size_t)row * N + col] =
          make_float2(acc[mt][nt][0] * escale, acc[mt][nt][1] * escale);
      *(float2*)&C[(size_t)(row + 8) * N + col] =
          make_float2(acc[mt][nt][2] * escale, acc[mt][nt][3] * escale);
    }
  }
}

// ---------------- inv_freq table ----------------
__global__ void invf_init() {
  int i = threadIdx.x;
  if (i < 128)
    g_invf[i] = exp(((double)(-2.0 * i) / 256.0) * 9.210340371976184);
}

// ---------------- RoPE + V convert: one thread per (row, i) --------------
// sincos computed ONCE per (row, i); loops over heads (coalesced).
__global__ __launch_bounds__(128) void rope_kernel(const int* __restrict__ pos) {
  const int i   = threadIdx.x;            // 0..127
  const int row = blockIdx.x;             // 0..4095
  const int p = pos[row];
  double ang = (double)p * g_invf[i];
  const double INV2PI = 0.15915494309189535;
  const double TWOPI  = 6.283185307179586;
  int kk = __double2int_rn(ang * INV2PI);
  float fr = (float)(ang - TWOPI * (double)kk);
  float s, c;
  __sincosf(fr, &s, &c);
  const int b = row >> 11, sidx = row & 2047;
  const float inv64 = 1.0f / 64.0f;
  const float* base = g_qkv + (size_t)row * cQKV;

  #pragma unroll 4
  for (int hh = 0; hh < 32; hh++) {
    float x1 = base[hh * cHD + i];
    float x2 = base[hh * cHD + i + 128];
    float y1 = (x1 * c - x2 * s) * inv64;
    float y2 = (x2 * c + x1 * s) * inv64;
    bool isq = hh < 16;
    int head = isq ? hh : hh - 16;
    size_t o = ((size_t)(b * cNH + head) * cS + sidx) * cHD + i;
    if (isq) {
      y1 *= 0.0625f;
      y2 *= 0.0625f;
      g_qh[o]       = __float2half(y1);
      g_qh[o + 128] = __float2half(y2);
    } else {
      g_kh[o]       = __float2half(y1);
      g_kh[o + 128] = __float2half(y2);
    }
  }

  // V: no rotation, scale-convert
  const float* vbase = base + 2 * cQSZ;
  #pragma unroll 4
  for (int h = 0; h < 16; h++) {
    float x1 = vbase[h * cHD + i];
    float x2 = vbase[h * cHD + i + 128];
    size_t o = ((size_t)(b * cNH + h) * cS + sidx) * cHD + i;
    g_vh[o]       = __float2half(x1 * inv64);
    g_vh[o + 128] = __float2half(x2 * inv64);
  }
}

// ---------------- HMMA flash attention (fp16, 1-pass QK and PV) ----------
constexpr int FQST = 264;
constexpr int FPST = 72;
constexpr int F_QH = 0;
constexpr int F_KH = 1 * 64 * FQST;
constexpr int F_VH = 2 * 64 * FQST;
constexpr int F_PH = 3 * 64 * FQST;
constexpr int F_TOT = F_PH + 64 * FPST;
constexpr int FLASH_SMEM = F_TOT * 2 + 448 * 4;   // 112384 B -> 2 CTA/SM

__global__ __launch_bounds__(256, 2) void flash_hmma(__half* __restrict__ ath) {
  extern __shared__ __half smem[];
  const uint32_t sb = smem_u32(smem);
  float* fre  = (float*)(smem + F_TOT);
  float* m_s  = fre;
  float* l_s  = fre + 64;
  float* f_s  = fre + 128;
  float* rmax = fre + 192;
  float* rsum = fre + 320;

  const int qtile = gridDim.x - 1 - blockIdx.x;
  const int bh = blockIdx.y;
  const int b = bh >> 4, h = bh & 15;
  const int tid = threadIdx.x, lane = tid & 31, wid = tid >> 5;
  const int wm = wid & 3, wg = wid >> 2;
  const int q0 = qtile * 64;

  const __half* qhb = g_qh + ((size_t)bh * cS + q0) * cHD;
  const __half* khb = g_kh + (size_t)bh * cS * cHD;
  const __half* vhb = g_vh + (size_t)bh * cS * cHD;

  #define LOADP(gptr, soff)                                              \
    do {                                                                 \
      _Pragma("unroll")                                                  \
      for (int i_ = 0; i_ < 8; i_++) {                                   \
        int id_ = tid + 256 * i_;                                        \
        int r_ = id_ >> 5, c_ = id_ & 31;                                \
        CP_ASYNC16(sb + (uint32_t)((soff) + r_ * FQST + c_ * 8) * 2,     \
                   (gptr) + r_ * 256 + c_ * 8);                          \
      }                                                                  \
    } while (0)

  LOADP(qhb, F_QH);
  LOADP(khb, F_KH);
  CP_COMMIT();
  LOADP(vhb, F_VH);
  CP_COMMIT();

  if (tid < 64) { m_s[tid] = -1e30f; l_s[tid] = 0.0f; }

  float o[16][4];
  #pragma unroll
  for (int i = 0; i < 16; i++)
    #pragma unroll
    for (int j = 0; j < 4; j++) o[i][j] = 0.0f;

  const uint32_t pQh = sb + F_QH * 2;
  const uint32_t pKh = sb + F_KH * 2;
  const uint32_t pVh = sb + F_VH * 2;
  const uint32_t pPh = sb + F_PH * 2;

  const int arow = 16 * wm + (lane & 15);
  const int acol = (lane >> 4) * 8;
  const int brow = wg * 32 + (lane & 7) + (lane >> 4) * 8;
  const int bcol = ((lane >> 3) & 1) * 8;
  const int row0 = 16 * wm + (lane >> 2);

  for (int jt = 0; jt <= qtile; jt++) {
    CP_WAIT(1);
    __syncthreads();

    // ---- S = Q K^T (1 pass) ----
    float s[4][4];
    #pragma unroll
    for (int nt = 0; nt < 4; nt++)
      #pragma unroll
      for (int c = 0; c < 4; c++) s[nt][c] = 0.0f;

    #pragma unroll 4
    for (int ks = 0; ks < 16; ks++) {
      const int k0 = ks * 16;
      uint32_t aqh[4], bkh0[4], bkh1[4];
      LDSM4(aqh[0], aqh[1], aqh[2], aqh[3],
            pQh + (uint32_t)(arow * FQST + k0 + acol) * 2);
      uint32_t boff0 = (uint32_t)(brow * FQST + k0 + bcol) * 2;
      LDSM4(bkh0[0], bkh0[1], bkh0[2], bkh0[3], pKh + boff0);
      LDSM4(bkh1[0], bkh1[1], bkh1[2], bkh1[3],
            pKh + boff0 + 16 * FQST * 2);
      uint32_t* bhp[4] = {&bkh0[0], &bkh0[2], &bkh1[0], &bkh1[2]};
      #pragma unroll
      for (int nt = 0; nt < 4; nt++) mma16816(s[nt], aqh, bhp[nt]);
    }

    // ---- causal mask ----
    if (jt == qtile) {
      #pragma unroll
      for (int nt = 0; nt < 4; nt++)
        #pragma unroll
        for (int c = 0; c < 4; c++) {
          int kvloc = wg * 32 + nt * 8 + (lane & 3) * 2 + (c & 1);
          int qloc = 16 * wm + (lane >> 2) + 8 * (c >> 1);
          if (kvloc > qloc) s[nt][c] = -1e30f;
        }
    }

    // ---- row max ----
    float lm0 = -1e30f, lm1 = -1e30f;
    #pragma unroll
    for (int nt = 0; nt < 4; nt++) {
      lm0 = fmaxf(lm0, fmaxf(s[nt][0], s[nt][1]));
      lm1 = fmaxf(lm1, fmaxf(s[nt][2], s[nt][3]));
    }
    lm0 = fmaxf(lm0, __shfl_xor_sync(0xffffffffu, lm0, 1));
    lm0 = fmaxf(lm0, __shfl_xor_sync(0xffffffffu, lm0, 2));
    lm1 = fmaxf(lm1, __shfl_xor_sync(0xffffffffu, lm1, 1));
    lm1 = fmaxf(lm1, __shfl_xor_sync(0xffffffffu, lm1, 2));
    if ((lane & 3) == 0) {
      rmax[wg * 64 + row0] = lm0;
      rmax[wg * 64 + row0 + 8] = lm1;
    }
    __syncthreads();
    if (tid < 64) {
      float mo = m_s[tid];
      float mn = fmaxf(mo, fmaxf(rmax[tid], rmax[64 + tid]));
      f_s[tid] = __expf(mo - mn);
      m_s[tid] = mn;
    }
    __syncthreads();

    // ---- exp, P store (fp16), O rescale, row sums ----
    {
      float mn0 = m_s[row0], mn1 = m_s[row0 + 8];
      float sum0 = 0.0f, sum1 = 0.0f;
      #pragma unroll
      for (int nt = 0; nt < 4; nt++) {
        float p0 = __expf(s[nt][0] - mn0);
        float p1 = __expf(s[nt][1] - mn0);
        float p2 = __expf(s[nt][2] - mn1);
        float p3 = __expf(s[nt][3] - mn1);
        sum0 += p0 + p1;
        sum1 += p2 + p3;
        int col = wg * 32 + nt * 8 + (lane & 3) * 2;
        *(__half2*)(smem + F_PH + row0 * FPST + col) = mk_h2(p0, p1);
        *(__half2*)(smem + F_PH + (row0 + 8) * FPST + col) = mk_h2(p2, p3);
      }
      sum0 += __shfl_xor_sync(0xffffffffu, sum0, 1);
      sum0 += __shfl_xor_sync(0xffffffffu, sum0, 2);
      sum1 += __shfl_xor_sync(0xffffffffu, sum1, 1);
      sum1 += __shfl_xor_sync(0xffffffffu, sum1, 2);
      if ((lane & 3) == 0) {
        rsum[wg * 64 + row0] = sum0;
        rsum[wg * 64 + row0 + 8] = sum1;
      }
      float f0 = f_s[row0], f1 = f_s[row0 + 8];
      #pragma unroll
      for (int dt = 0; dt < 16; dt++) {
        o[dt][0] *= f0; o[dt][1] *= f0;
        o[dt][2] *= f1; o[dt][3] *= f1;
      }
    }

    CP_WAIT(0);
    __syncthreads();

    if (jt < qtile) {
      LOADP(khb + (jt + 1) * 64 * 256, F_KH);
      CP_COMMIT();
    }
    if (tid < 64) l_s[tid] = l_s[tid] * f_s[tid] + rsum[tid] + rsum[64 + tid];

    // ---- O += P V (1 pass) ----
    #pragma unroll
    for (int ks = 0; ks < 4; ks++) {
      const int k0 = ks * 16;
      uint32_t aph[4];
      LDSM4(aph[0], aph[1], aph[2], aph[3],
            pPh + (uint32_t)(arow * FPST + k0 + acol) * 2);
      const int vrow = k0 + (lane & 15);
      #pragma unroll
      for (int dt2 = 0; dt2 < 8; dt2++) {
        int dbase = wg * 128 + dt2 * 16 + (lane >> 4) * 8;
        uint32_t bvh[4];
        LDSM4T(bvh[0], bvh[1], bvh[2], bvh[3],
               pVh + (uint32_t)(vrow * FQST + dbase) * 2);
        mma16816(o[dt2 * 2], aph, &bvh[0]);
        mma16816(o[dt2 * 2 + 1], aph, &bvh[2]);
      }
    }
    __syncthreads();
    if (jt < qtile) {
      LOADP(vhb + (jt + 1) * 64 * 256, F_VH);
      CP_COMMIT();
    }
  }
  #undef LOADP

  // ---- epilogue: /l, write fp16 to [b,s,h*256+d] ----
  float rl0 = 1.0f / l_s[row0];
  float rl1 = 1.0f / l_s[row0 + 8];
  size_t g0 = ((size_t)(b * cS + q0 + row0)) * cQSZ + h * cHD;
  size_t g1 = g0 + 8 * cQSZ;
  #pragma unroll
  for (int dt = 0; dt < 16; dt++) {
    int col = wg * 128 + dt * 8 + (lane & 3) * 2;
    *(__half2*)(ath + g0 + col) = mk_h2(o[dt][0] * rl0, o[dt][1] * rl0);
    *(__half2*)(ath + g1 + col) = mk_h2(o[dt][2] * rl1, o[dt][3] * rl1);
  }
}

// ---------------- launch ----------------
extern "C" void kernel_launch(void* const* d_in, const int* in_sizes, int n_in,
                              void* d_out, int out_size) {
  (void)in_sizes; (void)n_in; (void)out_size;
  const float* hidden = (const float*)d_in[0];
  const int*   pos    = (const int*)d_in[1];
  const float* Wqkv   = (const float*)d_in[2];
  const float* Wo     = (const float*)d_in[3];
  float* out = (float*)d_out;

  float* qkv_p;
  __half *hidh, *w1h, *ath, *w2h;
  cudaGetSymbolAddress((void**)&qkv_p, g_qkv);
  cudaGetSymbolAddress((void**)&hidh, g_hid_h);
  cudaGetSymbolAddress((void**)&w1h, g_w1_h);
  cudaGetSymbolAddress((void**)&ath, g_at_h);
  cudaGetSymbolAddress((void**)&w2h, g_w2_h);

  cudaFuncSetAttribute(gemm_hmma,
                       cudaFuncAttributeMaxDynamicSharedMemorySize, G_SMEM);
  cudaFuncSetAttribute(flash_hmma,
                       cudaFuncAttributeMaxDynamicSharedMemorySize, FLASH_SMEM);

  invf_init<<<1, 128>>>();
  {
    int n4 = cM * cH / 4;
    conv_kernel<<<(n4 + 255) / 256, 256>>>(hidden, hidh, n4);
    tsplit_kernel<<<dim3(cQKV / 32, cH / 32), 256>>>(Wqkv, w1h, cH, cQKV);
    tsplit_kernel<<<dim3(cH / 32, cQSZ / 32), 256>>>(Wo, w2h, cQSZ, cH);
  }
  // QKV projection: 1 pass, 128x128 tile, 3-stage. C = 64 * qkv.
  gemm_hmma<<<dim3(cQKV / BN, cM / BM), 256, G_SMEM>>>(
      hidh, w1h, qkv_p, cM, cQKV, cH, 1.0f);
  // RoPE + V convert (sincos once per (row, i))
  rope_kernel<<<cM, 128>>>(pos);
  // flash attention (2 CTAs/SM)
  flash_hmma<<<dim3(cS / 64, cB * cNH), 256, FLASH_SMEM>>>(ath);
  // output projection: 1 pass, 128x128 tile, 3-stage. C = 64 * out -> /64.
  gemm_hmma<<<dim3(cH / BN, cM / BM), 256, G_SMEM>>>(
      ath, w2h, out, cM, cH, cQSZ, 1.0f / 64.0f);
}

// round 11
// speedup vs baseline: 1.2608x; 1.0122x over previous
#include <cuda_runtime.h>
#include <cuda_fp16.h>
#include <math.h>
#include <stdint.h>

// ---------------- problem constants ----------------
namespace {
constexpr int cB  = 2;
constexpr int cS  = 2048;
constexpr int cH  = 3072;
constexpr int cNH = 16;
constexpr int cHD = 256;
constexpr int cQSZ  = cNH * cHD;            // 4096
constexpr int cQKV  = 3 * cQSZ;             // 12288
constexpr int cM    = cB * cS;              // 4096 rows
}

// ---------------- scratch ----------------
__device__ float g_qkv[(size_t)cM * cQKV];          // fp32, = 64 * true qkv
__device__ __half g_hid_h[(size_t)cM * cH];         // hidden fp16
__device__ __half g_w1_h[(size_t)cQKV * cH];        // (64*Wqkv)^T fp16
__device__ __half g_at_h[(size_t)cM * cQSZ];        // attn out fp16
__device__ __half g_w2_h[(size_t)cH * cQSZ];        // (64*Wo)^T fp16
// head-major [bh][s][d] fp16 singles
__device__ __half g_qh[(size_t)cM * cQSZ];          // Q (softmax scale folded)
__device__ __half g_kh[(size_t)cM * cQSZ];
__device__ __half g_vh[(size_t)cM * cQSZ];
__device__ double g_invf[128];

// ---------------- helpers (base ISA, compute_103-safe) ----------------
__device__ __forceinline__ uint32_t smem_u32(const void* p) {
  uint32_t a;
  asm("{ .reg .u64 t; cvta.to.shared.u64 t, %1; cvt.u32.u64 %0, t; }"
      : "=r"(a) : "l"(p));
  return a;
}
#define CP_ASYNC16(dst, src) \
  asm volatile("cp.async.cg.shared.global [%0], [%1], 16;" :: "r"(dst), "l"(src))
#define CP_COMMIT() asm volatile("cp.async.commit_group;" ::: "memory")
#define CP_WAIT(n)  asm volatile("cp.async.wait_group %0;" :: "n"(n) : "memory")
#define LDSM4(r0, r1, r2, r3, addr) \
  asm volatile("ldmatrix.sync.aligned.m8n8.x4.shared.b16 {%0,%1,%2,%3}, [%4];" \
               : "=r"(r0), "=r"(r1), "=r"(r2), "=r"(r3) : "r"(addr))
#define LDSM4T(r0, r1, r2, r3, addr) \
  asm volatile("ldmatrix.sync.aligned.m8n8.x4.trans.shared.b16 {%0,%1,%2,%3}, [%4];" \
               : "=r"(r0), "=r"(r1), "=r"(r2), "=r"(r3) : "r"(addr))

__device__ __forceinline__ void mma16816(float* d, const uint32_t* a,
                                         const uint32_t* b) {
  asm volatile(
      "mma.sync.aligned.m16n8k16.row.col.f32.f16.f16.f32 "
      "{%0,%1,%2,%3}, {%4,%5,%6,%7}, {%8,%9}, {%0,%1,%2,%3};"
      : "+f"(d[0]), "+f"(d[1]), "+f"(d[2]), "+f"(d[3])
      : "r"(a[0]), "r"(a[1]), "r"(a[2]), "r"(a[3]), "r"(b[0]), "r"(b[1]));
}

__device__ __forceinline__ __half2 mk_h2(float a, float b) {
  return __halves2half2(__float2half(a), __float2half(b));
}

// ---------------- hidden fp32 -> fp16 ----------------
__global__ __launch_bounds__(256) void conv_kernel(
    const float* __restrict__ x, __half* __restrict__ h, int n4) {
  int i = blockIdx.x * 256 + threadIdx.x;
  if (i >= n4) return;
  float4 v = ((const float4*)x)[i];
  ((__half2*)h)[2 * i]     = mk_h2(v.x, v.y);
  ((__half2*)h)[2 * i + 1] = mk_h2(v.z, v.w);
}

// ---------------- transpose + scale(64) -> fp16 ----------------
__global__ __launch_bounds__(256) void tsplit_kernel(
    const float* __restrict__ W, __half* __restrict__ Th, int K, int N) {
  __shared__ float sm[32][33];
  int n0 = blockIdx.x * 32, k0 = blockIdx.y * 32;
  int tx = threadIdx.x & 31, ty = threadIdx.x >> 5;
  #pragma unroll
  for (int q = 0; q < 4; q++)
    sm[ty + 8 * q][tx] = W[(size_t)(k0 + ty + 8 * q) * N + n0 + tx];
  __syncthreads();
  #pragma unroll
  for (int q = 0; q < 4; q++) {
    float x = sm[tx][ty + 8 * q] * 64.0f;
    Th[(size_t)(n0 + ty + 8 * q) * K + k0 + tx] = __float2half(x);
  }
}

// ---------------- HMMA GEMM 128x128x32, 4-stage, 2 CTA/SM ----------------
constexpr int BM = 128, BN = 128, BKt = 32;
constexpr int AST = 40;                      // smem row stride (halves)
constexpr int PARTE = BM * AST;              // halves per part (A or B)
constexpr int STAGEB = 2 * PARTE * 2;        // 20480 bytes per stage
constexpr int G_SMEM = 4 * STAGEB;           // 81920

__global__ __launch_bounds__(256, 2) void gemm_hmma(
    const __half* __restrict__ Ah, const __half* __restrict__ Bh,
    float* __restrict__ C, int M, int N, int K, float escale) {
  extern __shared__ __half smb[];
  const uint32_t sbase = smem_u32(smb);
  const int tid = threadIdx.x, lane = tid & 31, wid = tid >> 5;
  const int m0 = blockIdx.y * BM, n0 = blockIdx.x * BN;
  const int wm = (wid & 1) * 64, wn = (wid >> 1) * 32;

  float acc[4][4][4];
  #pragma unroll
  for (int i = 0; i < 4; i++)
    #pragma unroll
    for (int j = 0; j < 4; j++)
      #pragma unroll
      for (int q = 0; q < 4; q++) acc[i][j][q] = 0.0f;

  const int T = K / BKt;
  const int lr = tid >> 2, lc = tid & 3;     // loader row / 16B-chunk

  #define ISSUE(t)                                                          \
    do {                                                                    \
      int k0_ = (t) * BKt;                                                  \
      uint32_t db_ = sbase + ((t) & 3) * STAGEB;                            \
      _Pragma("unroll")                                                     \
      for (int i_ = 0; i_ < 2; i_++) {                                      \
        int r_ = lr + i_ * 64;                                              \
        uint32_t o_ = (r_ * AST + lc * 8) * 2;                              \
        CP_ASYNC16(db_ + o_, Ah + (size_t)(m0 + r_) * K + k0_ + lc * 8);    \
        CP_ASYNC16(db_ + PARTE * 2 + o_,                                    \
                   Bh + (size_t)(n0 + r_) * K + k0_ + lc * 8);              \
      }                                                                     \
    } while (0)

  ISSUE(0); CP_COMMIT();
  ISSUE(1); CP_COMMIT();
  ISSUE(2); CP_COMMIT();

  for (int t = 0; t < T; t++) {
    CP_WAIT(2);            // stage t landed
    __syncthreads();       // everyone past reads of stage (t-1)&3
    if (t + 3 < T) { ISSUE(t + 3); CP_COMMIT(); }

    uint32_t base = sbase + (t & 3) * STAGEB;
    const uint32_t pA = base;
    const uint32_t pB = base + PARTE * 2;

    #pragma unroll
    for (int ks = 0; ks < 2; ks++) {
      const int kb = ks * 16;
      uint32_t a[4][4], b[4][2];
      #pragma unroll
      for (int mt = 0; mt < 4; mt++) {
        int r = wm + mt * 16 + (lane & 15);
        int c = kb + ((lane >> 4) << 3);
        LDSM4(a[mt][0], a[mt][1], a[mt][2], a[mt][3],
              pA + (uint32_t)(r * AST + c) * 2);
      }
      #pragma unroll
      for (int p = 0; p < 2; p++) {
        int g = lane >> 3;
        int r = wn + (p * 2 + (g >> 1)) * 8 + (lane & 7);
        int c = kb + ((g & 1) << 3);
        LDSM4(b[2 * p][0], b[2 * p][1], b[2 * p + 1][0], b[2 * p + 1][1],
              pB + (uint32_t)(r * AST + c) * 2);
      }
      #pragma unroll
      for (int mt = 0; mt < 4; mt++)
        #pragma unroll
        for (int nt = 0; nt < 4; nt++) mma16816(acc[mt][nt], a[mt], b[nt]);
    }
  }
  #undef ISSUE

  #pragma unroll
  for (int mt = 0; mt < 4; mt++) {
    int row = m0 + wm + mt * 16 + (lane >> 2);
    #pragma unroll
    for (int nt = 0; nt < 4; nt++) {
      int col = n0 + wn + nt * 8 + ((lane & 3) << 1);
      *(float2*)&C[(size_t)row * N + col] =
          make_float2(acc[mt][nt][0] * escale, acc[mt][nt][1] * escale);
      *(float2*)&C[(size_t)(row + 8) * N + col] =
          make_float2(acc[mt][nt][2] * escale, acc[mt][nt][3] * escale);
    }
  }
}

// ---------------- inv_freq table ----------------
__global__ void invf_init() {
  int i = threadIdx.x;
  if (i < 128)
    g_invf[i] = exp(((double)(-2.0 * i) / 256.0) * 9.210340371976184);
}

// ---------------- RoPE + V convert: one thread per (row, i) --------------
__global__ __launch_bounds__(128) void rope_kernel(const int* __restrict__ pos) {
  const int i   = threadIdx.x;            // 0..127
  const int row = blockIdx.x;             // 0..4095
  const int p = pos[row];
  double ang = (double)p * g_invf[i];
  const double INV2PI = 0.15915494309189535;
  const double TWOPI  = 6.283185307179586;
  int kk = __double2int_rn(ang * INV2PI);
  float fr = (float)(ang - TWOPI * (double)kk);
  float s, c;
  __sincosf(fr, &s, &c);
  const int b = row >> 11, sidx = row & 2047;
  const float inv64 = 1.0f / 64.0f;
  const float* base = g_qkv + (size_t)row * cQKV;

  #pragma unroll 4
  for (int hh = 0; hh < 32; hh++) {
    float x1 = base[hh * cHD + i];
    float x2 = base[hh * cHD + i + 128];
    float y1 = (x1 * c - x2 * s) * inv64;
    float y2 = (x2 * c + x1 * s) * inv64;
    bool isq = hh < 16;
    int head = isq ? hh : hh - 16;
    size_t o = ((size_t)(b * cNH + head) * cS + sidx) * cHD + i;
    if (isq) {
      y1 *= 0.0625f;
      y2 *= 0.0625f;
      g_qh[o]       = __float2half(y1);
      g_qh[o + 128] = __float2half(y2);
    } else {
      g_kh[o]       = __float2half(y1);
      g_kh[o + 128] = __float2half(y2);
    }
  }

  // V: no rotation, scale-convert
  const float* vbase = base + 2 * cQSZ;
  #pragma unroll 4
  for (int h = 0; h < 16; h++) {
    float x1 = vbase[h * cHD + i];
    float x2 = vbase[h * cHD + i + 128];
    size_t o = ((size_t)(b * cNH + h) * cS + sidx) * cHD + i;
    g_vh[o]       = __float2half(x1 * inv64);
    g_vh[o + 128] = __float2half(x2 * inv64);
  }
}

// ---------------- HMMA flash attention (fp16, 1-pass QK and PV) ----------
constexpr int FQST = 264;
constexpr int FPST = 72;
constexpr int F_QH = 0;
constexpr int F_KH = 1 * 64 * FQST;
constexpr int F_VH = 2 * 64 * FQST;
constexpr int F_PH = 3 * 64 * FQST;
constexpr int F_TOT = F_PH + 64 * FPST;
constexpr int FLASH_SMEM = F_TOT * 2 + 448 * 4;   // 112384 B -> 2 CTA/SM

__global__ __launch_bounds__(256, 2) void flash_hmma(__half* __restrict__ ath) {
  extern __shared__ __half smem[];
  const uint32_t sb = smem_u32(smem);
  float* fre  = (float*)(smem + F_TOT);
  float* m_s  = fre;
  float* l_s  = fre + 64;
  float* f_s  = fre + 128;
  float* rmax = fre + 192;
  float* rsum = fre + 320;

  const int qtile = gridDim.x - 1 - blockIdx.x;
  const int bh = blockIdx.y;
  const int b = bh >> 4, h = bh & 15;
  const int tid = threadIdx.x, lane = tid & 31, wid = tid >> 5;
  const int wm = wid & 3, wg = wid >> 2;
  const int q0 = qtile * 64;

  const __half* qhb = g_qh + ((size_t)bh * cS + q0) * cHD;
  const __half* khb = g_kh + (size_t)bh * cS * cHD;
  const __half* vhb = g_vh + (size_t)bh * cS * cHD;

  #define LOADP(gptr, soff)                                              \
    do {                                                                 \
      _Pragma("unroll")                                                  \
      for (int i_ = 0; i_ < 8; i_++) {                                   \
        int id_ = tid + 256 * i_;                                        \
        int r_ = id_ >> 5, c_ = id_ & 31;                                \
        CP_ASYNC16(sb + (uint32_t)((soff) + r_ * FQST + c_ * 8) * 2,     \
                   (gptr) + r_ * 256 + c_ * 8);                          \
      }                                                                  \
    } while (0)

  LOADP(qhb, F_QH);
  LOADP(khb, F_KH);
  CP_COMMIT();
  LOADP(vhb, F_VH);
  CP_COMMIT();

  if (tid < 64) { m_s[tid] = -1e30f; l_s[tid] = 0.0f; }

  float o[16][4];
  #pragma unroll
  for (int i = 0; i < 16; i++)
    #pragma unroll
    for (int j = 0; j < 4; j++) o[i][j] = 0.0f;

  const uint32_t pQh = sb + F_QH * 2;
  const uint32_t pKh = sb + F_KH * 2;
  const uint32_t pVh = sb + F_VH * 2;
  const uint32_t pPh = sb + F_PH * 2;

  const int arow = 16 * wm + (lane & 15);
  const int acol = (lane >> 4) * 8;
  const int brow = wg * 32 + (lane & 7) + (lane >> 4) * 8;
  const int bcol = ((lane >> 3) & 1) * 8;
  const int row0 = 16 * wm + (lane >> 2);

  for (int jt = 0; jt <= qtile; jt++) {
    CP_WAIT(1);
    __syncthreads();

    // ---- S = Q K^T (1 pass) ----
    float s[4][4];
    #pragma unroll
    for (int nt = 0; nt < 4; nt++)
      #pragma unroll
      for (int c = 0; c < 4; c++) s[nt][c] = 0.0f;

    #pragma unroll 4
    for (int ks = 0; ks < 16; ks++) {
      const int k0 = ks * 16;
      uint32_t aqh[4], bkh0[4], bkh1[4];
      LDSM4(aqh[0], aqh[1], aqh[2], aqh[3],
            pQh + (uint32_t)(arow * FQST + k0 + acol) * 2);
      uint32_t boff0 = (uint32_t)(brow * FQST + k0 + bcol) * 2;
      LDSM4(bkh0[0], bkh0[1], bkh0[2], bkh0[3], pKh + boff0);
      LDSM4(bkh1[0], bkh1[1], bkh1[2], bkh1[3],
            pKh + boff0 + 16 * FQST * 2);
      uint32_t* bhp[4] = {&bkh0[0], &bkh0[2], &bkh1[0], &bkh1[2]};
      #pragma unroll
      for (int nt = 0; nt < 4; nt++) mma16816(s[nt], aqh, bhp[nt]);
    }

    // ---- causal mask ----
    if (jt == qtile) {
      #pragma unroll
      for (int nt = 0; nt < 4; nt++)
        #pragma unroll
        for (int c = 0; c < 4; c++) {
          int kvloc = wg * 32 + nt * 8 + (lane & 3) * 2 + (c & 1);
          int qloc = 16 * wm + (lane >> 2) + 8 * (c >> 1);
          if (kvloc > qloc) s[nt][c] = -1e30f;
        }
    }

    // ---- row max ----
    float lm0 = -1e30f, lm1 = -1e30f;
    #pragma unroll
    for (int nt = 0; nt < 4; nt++) {
      lm0 = fmaxf(lm0, fmaxf(s[nt][0], s[nt][1]));
      lm1 = fmaxf(lm1, fmaxf(s[nt][2], s[nt][3]));
    }
    lm0 = fmaxf(lm0, __shfl_xor_sync(0xffffffffu, lm0, 1));
    lm0 = fmaxf(lm0, __shfl_xor_sync(0xffffffffu, lm0, 2));
    lm1 = fmaxf(lm1, __shfl_xor_sync(0xffffffffu, lm1, 1));
    lm1 = fmaxf(lm1, __shfl_xor_sync(0xffffffffu, lm1, 2));
    if ((lane & 3) == 0) {
      rmax[wg * 64 + row0] = lm0;
      rmax[wg * 64 + row0 + 8] = lm1;
    }
    __syncthreads();
    if (tid < 64) {
      float mo = m_s[tid];
      float mn = fmaxf(mo, fmaxf(rmax[tid], rmax[64 + tid]));
      f_s[tid] = __expf(mo - mn);
      m_s[tid] = mn;
    }
    __syncthreads();

    // ---- exp, P store (fp16), O rescale, row sums ----
    {
      float mn0 = m_s[row0], mn1 = m_s[row0 + 8];
      float sum0 = 0.0f, sum1 = 0.0f;
      #pragma unroll
      for (int nt = 0; nt < 4; nt++) {
        float p0 = __expf(s[nt][0] - mn0);
        float p1 = __expf(s[nt][1] - mn0);
        float p2 = __expf(s[nt][2] - mn1);
        float p3 = __expf(s[nt][3] - mn1);
        sum0 += p0 + p1;
        sum1 += p2 + p3;
        int col = wg * 32 + nt * 8 + (lane & 3) * 2;
        *(__half2*)(smem + F_PH + row0 * FPST + col) = mk_h2(p0, p1);
        *(__half2*)(smem + F_PH + (row0 + 8) * FPST + col) = mk_h2(p2, p3);
      }
      sum0 += __shfl_xor_sync(0xffffffffu, sum0, 1);
      sum0 += __shfl_xor_sync(0xffffffffu, sum0, 2);
      sum1 += __shfl_xor_sync(0xffffffffu, sum1, 1);
      sum1 += __shfl_xor_sync(0xffffffffu, sum1, 2);
      if ((lane & 3) == 0) {
        rsum[wg * 64 + row0] = sum0;
        rsum[wg * 64 + row0 + 8] = sum1;
      }
      float f0 = f_s[row0], f1 = f_s[row0 + 8];
      #pragma unroll
      for (int dt = 0; dt < 16; dt++) {
        o[dt][0] *= f0; o[dt][1] *= f0;
        o[dt][2] *= f1; o[dt][3] *= f1;
      }
    }

    CP_WAIT(0);
    __syncthreads();

    if (jt < qtile) {
      LOADP(khb + (jt + 1) * 64 * 256, F_KH);
      CP_COMMIT();
    }
    if (tid < 64) l_s[tid] = l_s[tid] * f_s[tid] + rsum[tid] + rsum[64 + tid];

    // ---- O += P V (1 pass) ----
    #pragma unroll
    for (int ks = 0; ks < 4; ks++) {
      const int k0 = ks * 16;
      uint32_t aph[4];
      LDSM4(aph[0], aph[1], aph[2], aph[3],
            pPh + (uint32_t)(arow * FPST + k0 + acol) * 2);
      const int vrow = k0 + (lane & 15);
      #pragma unroll
      for (int dt2 = 0; dt2 < 8; dt2++) {
        int dbase = wg * 128 + dt2 * 16 + (lane >> 4) * 8;
        uint32_t bvh[4];
        LDSM4T(bvh[0], bvh[1], bvh[2], bvh[3],
               pVh + (uint32_t)(vrow * FQST + dbase) * 2);
        mma16816(o[dt2 * 2], aph, &bvh[0]);
        mma16816(o[dt2 * 2 + 1], aph, &bvh[2]);
      }
    }
    __syncthreads();
    if (jt < qtile) {
      LOADP(vhb + (jt + 1) * 64 * 256, F_VH);
      CP_COMMIT();
    }
  }
  #undef LOADP

  // ---- epilogue: /l, write fp16 to [b,s,h*256+d] ----
  float rl0 = 1.0f / l_s[row0];
  float rl1 = 1.0f / l_s[row0 + 8];
  size_t g0 = ((size_t)(b * cS + q0 + row0)) * cQSZ + h * cHD;
  size_t g1 = g0 + 8 * cQSZ;
  #pragma unroll
  for (int dt = 0; dt < 16; dt++) {
    int col = wg * 128 + dt * 8 + (lane & 3) * 2;
    *(__half2*)(ath + g0 + col) = mk_h2(o[dt][0] * rl0, o[dt][1] * rl0);
    *(__half2*)(ath + g1 + col) = mk_h2(o[dt][2] * rl1, o[dt][3] * rl1);
  }
}

// ---------------- launch ----------------
extern "C" void kernel_launch(void* const* d_in, const int* in_sizes, int n_in,
                              void* d_out, int out_size) {
  (void)in_sizes; (void)n_in; (void)out_size;
  const float* hidden = (const float*)d_in[0];
  const int*   pos    = (const int*)d_in[1];
  const float* Wqkv   = (const float*)d_in[2];
  const float* Wo     = (const float*)d_in[3];
  float* out = (float*)d_out;

  float* qkv_p;
  __half *hidh, *w1h, *ath, *w2h;
  cudaGetSymbolAddress((void**)&qkv_p, g_qkv);
  cudaGetSymbolAddress((void**)&hidh, g_hid_h);
  cudaGetSymbolAddress((void**)&w1h, g_w1_h);
  cudaGetSymbolAddress((void**)&ath, g_at_h);
  cudaGetSymbolAddress((void**)&w2h, g_w2_h);

  cudaFuncSetAttribute(gemm_hmma,
                       cudaFuncAttributeMaxDynamicSharedMemorySize, G_SMEM);
  cudaFuncSetAttribute(flash_hmma,
                       cudaFuncAttributeMaxDynamicSharedMemorySize, FLASH_SMEM);

  // Launch order arranged so the QKV GEMM is the 4th launch (ncu capture slot).
  {
    int n4 = cM * cH / 4;
    conv_kernel<<<(n4 + 255) / 256, 256>>>(hidden, hidh, n4);          // #1
    tsplit_kernel<<<dim3(cQKV / 32, cH / 32), 256>>>(Wqkv, w1h, cH, cQKV); // #2
    tsplit_kernel<<<dim3(cH / 32, cQSZ / 32), 256>>>(Wo, w2h, cQSZ, cH);   // #3
  }
  // QKV projection: 1 pass, 128x128 tile, 4-stage. C = 64 * qkv.   (#4)
  gemm_hmma<<<dim3(cQKV / BN, cM / BM), 256, G_SMEM>>>(
      hidh, w1h, qkv_p, cM, cQKV, cH, 1.0f);
  invf_init<<<1, 128>>>();                                            // #5
  // RoPE + V convert (sincos once per (row, i))                     (#6)
  rope_kernel<<<cM, 128>>>(pos);
  // flash attention (2 CTAs/SM)                                     (#7)
  flash_hmma<<<dim3(cS / 64, cB * cNH), 256, FLASH_SMEM>>>(ath);
  // output projection: 1 pass, 128x128 tile, 4-stage. C = 64*out -> /64. (#8)
  gemm_hmma<<<dim3(cH / BN, cM / BM), 256, G_SMEM>>>(
      ath, w2h, out, cM, cH, cQSZ, 1.0f / 64.0f);
}